// round 1
// baseline (speedup 1.0000x reference)
#include <cuda_runtime.h>
#include <math.h>

// Problem constants (fixed by setup_inputs)
#define WINC   20
#define OFFSETC 40
#define FDIM   8192
#define CDIM   256
#define PDIM   256
#define MAXB   64
#define SIL_CHUNKS 32   // FDIM / 256

__device__ float g_part_a[MAXB];            // per-batch phoneme-loss partials
__device__ float g_part_b[MAXB * SIL_CHUNKS]; // per (batch, chunk) silence partials

__device__ __forceinline__ float block_reduce_sum(float v) {
    __shared__ float sh[32];
    int lane = threadIdx.x & 31;
    int w    = threadIdx.x >> 5;
    #pragma unroll
    for (int o = 16; o; o >>= 1) v += __shfl_down_sync(0xffffffffu, v, o);
    if (lane == 0) sh[w] = v;
    __syncthreads();
    int nw = (blockDim.x + 31) >> 5;
    v = (threadIdx.x < nw) ? sh[threadIdx.x] : 0.0f;
    if (w == 0) {
        #pragma unroll
        for (int o = 16; o; o >>= 1) v += __shfl_down_sync(0xffffffffu, v, o);
    }
    return v;
}

// One block per batch, one thread per phoneme p.
__global__ void phoneme_kernel(const float* __restrict__ X,
                               const int* __restrict__ lengths,
                               const int* __restrict__ tgt,
                               const int* __restrict__ p_end,
                               const int* __restrict__ pnum) {
    int b = blockIdx.x;
    int p = threadIdx.x;
    int len = lengths[b];
    int pn  = pnum[b];

    float contrib = 0.0f;
    if (p < pn) {
        int ends_ph = min(p_end[b] + OFFSETC, len);
        int start   = max(ends_ph - WINC * (pn - p), 0);
        int end     = min(start + WINC, len);
        int wlen    = end - start;
        int c       = tgt[b * PDIM + p];
        const float* xb = X + (size_t)b * FDIM * CDIM;

        float v[WINC];
        #pragma unroll
        for (int t = 0; t < WINC; t++) {
            int fi = start + t;
            fi = fi < (FDIM - 1) ? fi : (FDIM - 1);
            v[t] = (t < wlen) ? xb[(size_t)fi * CDIM + c] : 0.0f;
        }

        // Gaussian taps: g[i] = exp(-0.5*((i-4)/4)^2), normalized (float32, like jnp)
        float g[9];
        float s = 0.0f;
        #pragma unroll
        for (int i = 0; i < 9; i++) {
            float x = (float)(i - 4) * 0.25f;
            g[i] = expf(-0.5f * x * x);
            s += g[i];
        }
        #pragma unroll
        for (int i = 0; i < 9; i++) g[i] = g[i] / s;

        // smoothed[k] = sum_{i=0..8} g[i] * v[k + i - 3]  (zero outside [0,WIN))
        float m = -INFINITY;
        #pragma unroll
        for (int k = 0; k < WINC; k++) {
            if (k < wlen) {
                float sm = 0.0f;
                #pragma unroll
                for (int i = 0; i < 9; i++) {
                    int idx = k + i - 3;
                    if (idx >= 0 && idx < WINC) sm += g[i] * v[idx];
                }
                m = fmaxf(m, sm);
            }
        }
        contrib = -m;
    }

    float tot = block_reduce_sum(contrib);
    if (threadIdx.x == 0) g_part_a[b] = tot;
}

// grid = (SIL_CHUNKS, B), 256 threads; each thread handles one frame.
__global__ void sil_kernel(const float* __restrict__ X,
                           const int* __restrict__ lengths,
                           const int* __restrict__ p_end,
                           const int* __restrict__ pnum) {
    int b  = blockIdx.y;
    int tf = blockIdx.x * blockDim.x + threadIdx.x;
    int len = lengths[b];
    int pn  = pnum[b];
    int ends_ph = min(p_end[b] + OFFSETC, len);
    int first_start = max(ends_ph - WINC * pn, 0);
    int sl = max(ends_ph - WINC, 0);           // start of last valid phoneme (p = pn-1)
    int last_end = min(sl + WINC, len);

    float contrib = 0.0f;
    // mask = (tf < first_start) | ((tf >= last_end) & (tf < len))   [Python precedence]
    if (tf < FDIM && ((tf < first_start) || ((tf >= last_end) && (tf < len)))) {
        contrib = -X[((size_t)b * FDIM + tf) * CDIM];  // column SIL = 0
    }

    float tot = block_reduce_sum(contrib);
    if (threadIdx.x == 0) g_part_b[b * gridDim.x + blockIdx.x] = tot;
}

// Deterministic final reduction: fixed strided order, single block.
__global__ void reduce_kernel(float* __restrict__ out, int B, int nchunks) {
    float v = 0.0f;
    int nb = B * nchunks;
    for (int i = threadIdx.x; i < nb; i += blockDim.x) v += g_part_b[i];
    for (int i = threadIdx.x; i < B; i += blockDim.x) v += g_part_a[i];
    float tot = block_reduce_sum(v);
    if (threadIdx.x == 0) out[0] = tot;
}

extern "C" void kernel_launch(void* const* d_in, const int* in_sizes, int n_in,
                              void* d_out, int out_size) {
    const float* X       = (const float*)d_in[0];
    const int*   lengths = (const int*)d_in[1];
    const int*   tgt     = (const int*)d_in[2];
    const int*   p_end   = (const int*)d_in[3];
    const int*   pnum    = (const int*)d_in[4];
    float*       out     = (float*)d_out;

    int B = in_sizes[1];  // lengths has B elements

    phoneme_kernel<<<B, PDIM>>>(X, lengths, tgt, p_end, pnum);
    sil_kernel<<<dim3(SIL_CHUNKS, B), 256>>>(X, lengths, p_end, pnum);
    reduce_kernel<<<1, 256>>>(out, B, SIL_CHUNKS);
}

// round 2
// speedup vs baseline: 1.3692x; 1.3692x over previous
#include <cuda_runtime.h>
#include <math.h>

// Problem constants (fixed by setup_inputs)
#define WINC    20
#define OFFSETC 40
#define FDIM    8192
#define CDIM    256
#define PDIM    256
#define SIL_CHUNKS 32          // FDIM / 256
#define PH_BLOCKS  1024        // B*P / 8 warps  (B=32, P=256)
#define SIL_BLOCKS 1024        // B * SIL_CHUNKS
#define NPART      (PH_BLOCKS + SIL_BLOCKS)

__device__ float g_part[NPART];

__device__ __forceinline__ float block_reduce_sum(float v) {
    __shared__ float sh[32];
    int lane = threadIdx.x & 31;
    int w    = threadIdx.x >> 5;
    #pragma unroll
    for (int o = 16; o; o >>= 1) v += __shfl_down_sync(0xffffffffu, v, o);
    if (lane == 0) sh[w] = v;
    __syncthreads();
    int nw = (blockDim.x + 31) >> 5;
    v = (threadIdx.x < nw) ? sh[threadIdx.x] : 0.0f;
    if (w == 0) {
        #pragma unroll
        for (int o = 16; o; o >>= 1) v += __shfl_down_sync(0xffffffffu, v, o);
    }
    return v;
}

// Fused kernel.
//  blocks [0, PH_BLOCKS): phoneme loss, one warp per (b,p), 8 warps/block.
//  blocks [PH_BLOCKS, PH_BLOCKS+SIL_BLOCKS): silence term, 1 thread/frame.
__global__ void fused_kernel(const float* __restrict__ X,
                             const int* __restrict__ lengths,
                             const int* __restrict__ tgt,
                             const int* __restrict__ p_end,
                             const int* __restrict__ pnum) {
    const unsigned FULL = 0xffffffffu;
    int bid  = blockIdx.x;
    int lane = threadIdx.x & 31;
    int wid  = threadIdx.x >> 5;

    float contrib = 0.0f;

    if (bid < PH_BLOCKS) {
        // ---------- phoneme term: warp per (b, p) ----------
        int w = (bid << 3) + wid;          // global warp id in [0, B*P)
        int b = w >> 8;                    // P = 256
        int p = w & 255;
        int len = lengths[b];
        int pn  = pnum[b];

        if (p < pn) {
            int ends_ph = min(p_end[b] + OFFSETC, len);
            int start   = max(ends_ph - WINC * (pn - p), 0);
            int wlen    = min(start + WINC, len) - start;
            int c       = tgt[b * PDIM + p];

            float v = 0.0f;
            if (lane < WINC && lane < wlen) {
                int fi = min(start + lane, FDIM - 1);
                v = X[((size_t)b * FDIM + fi) * CDIM + c];
            }

            // Gaussian taps (float32, identical arithmetic to jnp reference)
            float g[9];
            float s = 0.0f;
            #pragma unroll
            for (int i = 0; i < 9; i++) {
                float x = (float)(i - 4) * 0.25f;
                g[i] = expf(-0.5f * x * x);
                s += g[i];
            }
            #pragma unroll
            for (int i = 0; i < 9; i++) g[i] = g[i] / s;

            // smoothed[lane] = sum_i g[i] * v[lane + i - 3]; out-of-range -> 0
            // (idx & 31 wraps negatives onto lanes 29..31 which hold v = 0,
            //  and idx in [20,24] hits zero lanes too)
            float sm = 0.0f;
            #pragma unroll
            for (int i = 0; i < 9; i++) {
                int idx = lane + i - 3;
                float vi = __shfl_sync(FULL, v, idx & 31);
                sm += g[i] * vi;
            }

            float m = (lane < wlen && lane < WINC) ? sm : -INFINITY;
            #pragma unroll
            for (int o = 16; o; o >>= 1) m = fmaxf(m, __shfl_xor_sync(FULL, m, o));
            if (lane == 0) contrib = -m;
        }
        // reduce the 8 warp-lane0 contributions
        float tot = block_reduce_sum(contrib);
        if (threadIdx.x == 0) g_part[bid] = tot;
    } else {
        // ---------- silence term ----------
        int sb = bid - PH_BLOCKS;
        int b  = sb >> 5;                  // SIL_CHUNKS = 32
        int ch = sb & 31;
        int tf = ch * 256 + threadIdx.x;

        int len = lengths[b];
        int pn  = pnum[b];
        int ends_ph = min(p_end[b] + OFFSETC, len);
        int first_start = max(ends_ph - WINC * pn, 0);
        int sl = max(ends_ph - WINC, 0);
        int last_end = min(sl + WINC, len);

        // mask = (tf < first_start) | ((tf >= last_end) & (tf < len))
        if ((tf < first_start) || ((tf >= last_end) && (tf < len))) {
            contrib = -X[((size_t)b * FDIM + tf) * CDIM];   // SIL column = 0
        }
        float tot = block_reduce_sum(contrib);
        if (threadIdx.x == 0) g_part[bid] = tot;
    }
}

// Deterministic final reduction: fixed strided order, single block.
__global__ void reduce_kernel(float* __restrict__ out) {
    float v = 0.0f;
    for (int i = threadIdx.x; i < NPART; i += blockDim.x) v += g_part[i];
    float tot = block_reduce_sum(v);
    if (threadIdx.x == 0) out[0] = tot;
}

extern "C" void kernel_launch(void* const* d_in, const int* in_sizes, int n_in,
                              void* d_out, int out_size) {
    const float* X       = (const float*)d_in[0];
    const int*   lengths = (const int*)d_in[1];
    const int*   tgt     = (const int*)d_in[2];
    const int*   p_end   = (const int*)d_in[3];
    const int*   pnum    = (const int*)d_in[4];
    float*       out     = (float*)d_out;

    fused_kernel<<<NPART, 256>>>(X, lengths, tgt, p_end, pnum);
    reduce_kernel<<<1, 256>>>(out);
}

// round 3
// speedup vs baseline: 1.3894x; 1.0147x over previous
#include <cuda_runtime.h>
#include <math.h>

// Problem constants (fixed by setup_inputs)
#define WINC    20
#define OFFSETC 40
#define FDIM    8192
#define CDIM    256
#define PDIM    256
#define SIL_CHUNKS 32          // FDIM / 256
#define PH_BLOCKS  1024        // B*P / 8 warps  (B=32, P=256)
#define SIL_BLOCKS 1024        // B * SIL_CHUNKS
#define NPART      (PH_BLOCKS + SIL_BLOCKS)

__device__ float g_part[NPART];
__device__ unsigned int g_ticket = 0;

__device__ __forceinline__ float block_reduce_sum(float v) {
    __shared__ float sh[32];
    int lane = threadIdx.x & 31;
    int w    = threadIdx.x >> 5;
    #pragma unroll
    for (int o = 16; o; o >>= 1) v += __shfl_down_sync(0xffffffffu, v, o);
    if (lane == 0) sh[w] = v;
    __syncthreads();
    int nw = (blockDim.x + 31) >> 5;
    v = (threadIdx.x < nw) ? sh[threadIdx.x] : 0.0f;
    if (w == 0) {
        #pragma unroll
        for (int o = 16; o; o >>= 1) v += __shfl_down_sync(0xffffffffu, v, o);
    }
    return v;
}

// Fused single kernel.
//  blocks [0, PH_BLOCKS): phoneme loss, one warp per (b,p), 8 warps/block.
//  blocks [PH_BLOCKS, NPART): silence term, 1 thread/frame.
//  The last block to finish performs the deterministic final reduction.
__global__ void fused_kernel(const float* __restrict__ X,
                             const int* __restrict__ lengths,
                             const int* __restrict__ tgt,
                             const int* __restrict__ p_end,
                             const int* __restrict__ pnum,
                             float* __restrict__ out) {
    const unsigned FULL = 0xffffffffu;
    int bid  = blockIdx.x;
    int lane = threadIdx.x & 31;
    int wid  = threadIdx.x >> 5;

    float contrib = 0.0f;

    if (bid < PH_BLOCKS) {
        // ---------- phoneme term: warp per (b, p) ----------
        int w = (bid << 3) + wid;          // global warp id in [0, B*P)
        int b = w >> 8;                    // P = 256
        int p = w & 255;
        int len = lengths[b];
        int pn  = pnum[b];

        if (p < pn) {
            int ends_ph = min(p_end[b] + OFFSETC, len);
            int start   = max(ends_ph - WINC * (pn - p), 0);
            int wlen    = min(start + WINC, len) - start;
            int c       = tgt[b * PDIM + p];

            float v = 0.0f;
            if (lane < WINC && lane < wlen) {
                int fi = min(start + lane, FDIM - 1);
                v = X[((size_t)b * FDIM + fi) * CDIM + c];
            }

            // Gaussian taps (float32, identical arithmetic to jnp reference)
            float g[9];
            float s = 0.0f;
            #pragma unroll
            for (int i = 0; i < 9; i++) {
                float x = (float)(i - 4) * 0.25f;
                g[i] = expf(-0.5f * x * x);
                s += g[i];
            }
            #pragma unroll
            for (int i = 0; i < 9; i++) g[i] = g[i] / s;

            // smoothed[lane] = sum_i g[i] * v[lane + i - 3]; out-of-range -> 0
            // (idx & 31 wraps negatives onto lanes 29..31 which hold v = 0,
            //  and idx in [20,24] hits zero lanes too)
            float sm = 0.0f;
            #pragma unroll
            for (int i = 0; i < 9; i++) {
                int idx = lane + i - 3;
                float vi = __shfl_sync(FULL, v, idx & 31);
                sm += g[i] * vi;
            }

            float m = (lane < wlen && lane < WINC) ? sm : -INFINITY;
            #pragma unroll
            for (int o = 16; o; o >>= 1) m = fmaxf(m, __shfl_xor_sync(FULL, m, o));
            if (lane == 0) contrib = -m;
        }
    } else {
        // ---------- silence term ----------
        int sb = bid - PH_BLOCKS;
        int b  = sb >> 5;                  // SIL_CHUNKS = 32
        int ch = sb & 31;
        int tf = ch * 256 + threadIdx.x;

        int len = lengths[b];
        int pn  = pnum[b];
        int ends_ph = min(p_end[b] + OFFSETC, len);
        int first_start = max(ends_ph - WINC * pn, 0);
        int sl = max(ends_ph - WINC, 0);
        int last_end = min(sl + WINC, len);

        // mask = (tf < first_start) | ((tf >= last_end) & (tf < len))
        if ((tf < first_start) || ((tf >= last_end) && (tf < len))) {
            contrib = -X[((size_t)b * FDIM + tf) * CDIM];   // SIL column = 0
        }
    }

    float tot = block_reduce_sum(contrib);
    if (threadIdx.x == 0) g_part[bid] = tot;

    // ---------- last-block-done deterministic final reduction ----------
    __threadfence();
    __shared__ bool is_last;
    if (threadIdx.x == 0) {
        unsigned t = atomicAdd(&g_ticket, 1u);
        is_last = (t == (unsigned)(gridDim.x - 1));
    }
    __syncthreads();   // also separates the two uses of block_reduce's smem

    if (is_last) {
        float v = 0.0f;
        for (int i = threadIdx.x; i < NPART; i += blockDim.x) v += g_part[i];
        float total = block_reduce_sum(v);
        if (threadIdx.x == 0) {
            out[0] = total;
            g_ticket = 0;    // reset for the next graph replay
        }
    }
}

extern "C" void kernel_launch(void* const* d_in, const int* in_sizes, int n_in,
                              void* d_out, int out_size) {
    const float* X       = (const float*)d_in[0];
    const int*   lengths = (const int*)d_in[1];
    const int*   tgt     = (const int*)d_in[2];
    const int*   p_end   = (const int*)d_in[3];
    const int*   pnum    = (const int*)d_in[4];
    float*       out     = (float*)d_out;

    fused_kernel<<<NPART, 256>>>(X, lengths, tgt, p_end, pnum, out);
}